// round 5
// baseline (speedup 1.0000x reference)
#include <cuda_runtime.h>
#include <math.h>
#include <stdint.h>

// ---------------------------------------------------------------------------
// GridFeatureToPointGraphConv — R5: cp.async (LDGSTS) staging of all 16 Gpre
// rows into the h1s slot right after selection (MLP 16, one wait), pre-phase
// MLP moved after the async issue to overlap the copy latency.
// Numerics identical to R4.
// ---------------------------------------------------------------------------

#define RES 48
#define NGRID (RES*RES*RES)      // 110592
#define NPTS 65536
#define HID 64
#define KNN 16

typedef unsigned long long u64;

__device__ float g_Gpre[NGRID * HID];   // 28.3 MB scratch (L2-resident)
__device__ u64   g_W2p[32 * 32];        // {W2[2i][o], W2[2i+1][o]} pairs
__device__ u64   g_W3p[16 * 32];        // {W3[2i][o], W3[2i+1][o]} pairs

// ---- f32x2 helpers -------------------------------------------------------
__device__ __forceinline__ u64 pack2(float lo, float hi) {
    u64 r; asm("mov.b64 %0, {%1,%2};" : "=l"(r) : "f"(lo), "f"(hi)); return r;
}
__device__ __forceinline__ void unpack2(u64 v, float& lo, float& hi) {
    asm("mov.b64 {%0,%1}, %2;" : "=f"(lo), "=f"(hi) : "l"(v));
}
__device__ __forceinline__ u64 fma2(u64 a, u64 b, u64 c) {
    u64 d; asm("fma.rn.f32x2 %0, %1, %2, %3;" : "=l"(d) : "l"(a), "l"(b), "l"(c)); return d;
}
__device__ __forceinline__ u64 mul2(u64 a, u64 b) {
    u64 d; asm("mul.rn.f32x2 %0, %1, %2;" : "=l"(d) : "l"(a), "l"(b)); return d;
}
__device__ __forceinline__ u64 add2(u64 a, u64 b) {
    u64 d; asm("add.rn.f32x2 %0, %1, %2;" : "=l"(d) : "l"(a), "l"(b)); return d;
}
__device__ __forceinline__ float ex2f(float x) {
    float r; asm("ex2.approx.f32 %0, %1;" : "=f"(r) : "f"(x)); return r;
}
__device__ __forceinline__ float rcpf(float x) {
    float r; asm("rcp.approx.f32 %0, %1;" : "=f"(r) : "f"(x)); return r;
}
__device__ __forceinline__ uint32_t s2u(const void* p) {
    return (uint32_t)__cvta_generic_to_shared(p);
}
__device__ __forceinline__ void cp_async8(uint32_t dst, const void* src) {
    asm volatile("cp.async.ca.shared.global [%0], [%1], 8;" :: "r"(dst), "l"(src));
}

// gelu_tanh(x) == x / (1 + e^{-p}), p = 1.5957691216x + 0.07135481681x^3
__device__ __forceinline__ float gelu_fast(float x) {
    float u = x * x;
    float w = __fmaf_rn(0.07135481681f, u, 1.5957691216f);
    float p = x * w;
    float e = __expf(-p);
    return __fdividef(x, 1.0f + e);
}

// paired gelu: componentwise identical rounding to gelu_fast
__device__ __forceinline__ u64 gelu2(u64 x, u64 C0, u64 C1, u64 NL2E, u64 ONE2) {
    u64 u = mul2(x, x);
    u64 w = fma2(u, C0, C1);
    u64 p = mul2(x, w);
    u64 m = mul2(p, NL2E);
    float m0, m1; unpack2(m, m0, m1);
    u64 e = pack2(ex2f(m0), ex2f(m1));
    u64 den = add2(ONE2, e);
    float d0, d1; unpack2(den, d0, d1);
    u64 r = pack2(rcpf(d0), rcpf(d1));
    return mul2(x, r);
}

// ---------------------------------------------------------------------------
// Kernel 1: Gpre[g][i] = sum_c grid_features[g][c] * W1[c][i]   (rows 0..31)
//           + pack W2/W3 pair tables (block 0)
// ---------------------------------------------------------------------------
__global__ __launch_bounds__(256) void gpre_kernel(const float* __restrict__ gf,
                                                   const float* __restrict__ W1,
                                                   const float* __restrict__ W2,
                                                   const float* __restrict__ W3) {
    __shared__ float W1s[32 * 64];
    __shared__ float gfs[4 * 32];
    int tid = threadIdx.x;
    for (int t = tid; t < 32 * 64; t += 256) W1s[t] = W1[t];

    if (blockIdx.x == 0) {
        for (int j = tid; j < 32 * 32; j += 256) {
            int i = j >> 5, o = j & 31;
            g_W2p[j] = pack2(W2[(2 * i) * 32 + o], W2[(2 * i + 1) * 32 + o]);
        }
        for (int j = tid; j < 16 * 32; j += 256) {
            int i = j >> 5, o = j & 31;
            g_W3p[j] = pack2(W3[(2 * i) * 32 + o], W3[(2 * i + 1) * 32 + o]);
        }
    }

    int i = tid & 63;
    int v = tid >> 6;
    int base = blockIdx.x * 32;

    for (int it = 0; it < 8; ++it) {
        int g = base + it * 4;
        __syncthreads();
        if (tid < 128) gfs[tid] = gf[(size_t)g * 32 + tid];
        __syncthreads();
        float acc = 0.0f;
        #pragma unroll
        for (int c = 0; c < 32; ++c)
            acc = fmaf(gfs[v * 32 + c], W1s[c * 64 + i], acc);
        g_Gpre[(size_t)g * 64 + (size_t)tid] = acc;
    }
}

// ---------------------------------------------------------------------------
// Candidate distance, matching reference expansion: qq - 2*(q.p) + pp
// ---------------------------------------------------------------------------
__device__ __forceinline__ float cand_dist(int t, int ix0, int iy0, int iz0,
                                           const float* __restrict__ lins,
                                           float qx, float qy, float qz, float qq) {
    int a = t >> 4, b = (t >> 2) & 3, c = t & 3;
    float px = lins[ix0 + a], py = lins[iy0 + b], pz = lins[iz0 + c];
    float pp = __fadd_rn(__fadd_rn(__fmul_rn(px, px), __fmul_rn(py, py)), __fmul_rn(pz, pz));
    float dot = __fmaf_rn(qz, pz, __fmaf_rn(qy, py, __fmul_rn(qx, px)));
    return __fadd_rn(__fsub_rn(qq, __fadd_rn(dot, dot)), pp);
}

__device__ __forceinline__ unsigned int fmap(float d) {
    unsigned int b = __float_as_uint(d);
    return (b & 0x80000000u) ? ~b : (b | 0x80000000u);
}

__device__ __forceinline__ u64 bitonic_ce(u64 key, int j, bool up, int lane) {
    u64 pk = __shfl_xor_sync(0xffffffffu, key, j);
    bool lower = ((lane & j) == 0);
    u64 mn = (key < pk) ? key : pk;
    u64 mx = (key < pk) ? pk : key;
    return ((lower == up)) ? mn : mx;
}

// ---------------------------------------------------------------------------
// Kernel 2: fused KNN + edge MLP + mean + out MLP. One warp per point.
// ---------------------------------------------------------------------------
__global__ __launch_bounds__(256, 2) void fused_kernel(
    const float* __restrict__ gv,
    const float* __restrict__ pv,
    const float* __restrict__ pf,
    const float* __restrict__ W1,
    const float* __restrict__ b1,
    const float* __restrict__ b2,
    const float* __restrict__ b3,
    float* __restrict__ out)
{
    __shared__ float lins[RES];
    __shared__ __align__(16) float W1s[35 * 64];     // W1 rows 32..66 (self + rel)
    __shared__ float b1s[64];
    __shared__ float b2s[32];
    __shared__ float b3s[32];
    __shared__ __align__(16) float h1s[8][16][64];   // staging for Gpre, then h1
    __shared__ __align__(16) float aggs[8][32];

    int tid = threadIdx.x;
    for (int t = tid; t < 35 * 64; t += 256) W1s[t] = W1[32 * 64 + t];
    if (tid < 64) b1s[tid] = b1[tid];
    if (tid >= 64 && tid < 96)  b2s[tid - 64] = b2[tid - 64];
    if (tid >= 96 && tid < 128) b3s[tid - 96] = b3[tid - 96];
    if (tid >= 128 && tid < 128 + RES)
        lins[tid - 128] = __fmul_rn(gv[3 * (tid - 128) + 2], 24.0f);
    __syncthreads();

    const int w = tid >> 5;
    const int lane = tid & 31;
    const int p = blockIdx.x * 8 + w;

    const u64 C0   = pack2(0.07135481681f, 0.07135481681f);
    const u64 C1   = pack2(1.5957691216f, 1.5957691216f);
    const u64 NL2E = pack2(-1.442695041f, -1.442695041f);
    const u64 ONE2 = pack2(1.0f, 1.0f);

    // W2 pair-column for this lane (issued early; latency overlaps selection)
    u64 w2p[32];
    #pragma unroll
    for (int i2 = 0; i2 < 32; ++i2) w2p[i2] = __ldg(&g_W2p[i2 * 32 + lane]);

    // point coords (scaled)
    float qxu = __ldg(&pv[p * 3 + 0]);
    float qyu = __ldg(&pv[p * 3 + 1]);
    float qzu = __ldg(&pv[p * 3 + 2]);
    float qx = __fmul_rn(qxu, 24.0f);
    float qy = __fmul_rn(qyu, 24.0f);
    float qz = __fmul_rn(qzu, 24.0f);
    float qq = __fadd_rn(__fadd_rn(__fmul_rn(qx, qx), __fmul_rn(qy, qy)), __fmul_rn(qz, qz));

    // ---- Phase A: selection via bitonic sort of 64 (d, t) keys ----
    int ix0 = min(max((int)floorf((qxu + 1.0f) * 23.5f) - 1, 0), RES - 4);
    int iy0 = min(max((int)floorf((qyu + 1.0f) * 23.5f) - 1, 0), RES - 4);
    int iz0 = min(max((int)floorf((qzu + 1.0f) * 23.5f) - 1, 0), RES - 4);

    float dA = cand_dist(lane,      ix0, iy0, iz0, lins, qx, qy, qz, qq);
    float dB = cand_dist(lane + 32, ix0, iy0, iz0, lins, qx, qy, qz, qq);
    u64 key0 = ((u64)fmap(dA) << 32) | (unsigned int)lane;
    u64 key1 = ((u64)fmap(dB) << 32) | (unsigned int)(lane + 32);

    #pragma unroll
    for (int ks = 2; ks <= 32; ks <<= 1) {
        bool up0 = ((lane & ks) == 0);
        bool up1 = (((lane + 32) & ks) == 0);
        #pragma unroll
        for (int j = ks >> 1; j > 0; j >>= 1) {
            key0 = bitonic_ce(key0, j, up0, lane);
            key1 = bitonic_ce(key1, j, up1, lane);
        }
    }
    {   // final merge: keep min half, clean 5 levels
        key0 = (key0 < key1) ? key0 : key1;
        #pragma unroll
        for (int j = 16; j > 0; j >>= 1)
            key0 = bitonic_ce(key0, j, true, lane);
    }
    int myt = (int)((unsigned int)key0 & 63u);   // lane k (<16) holds rank-k neighbor

    // ---- Stage all 16 Gpre rows via cp.async (lane-local 8B each) ----
    const int gbase = ix0 * (RES * RES) + iy0 * RES + iz0;
    uint32_t h1base = s2u(&h1s[w][0][0]);
    #pragma unroll
    for (int k = 0; k < KNN; ++k) {
        int t = __shfl_sync(0xffffffffu, myt, k);
        int a = t >> 4, b = (t >> 2) & 3, c = t & 3;
        int gm = gbase + a * (RES * RES) + b * RES + c;
        cp_async8(h1base + (uint32_t)(k * 32 + lane) * 8u,
                  g_Gpre + (size_t)gm * 64 + 2 * lane);
    }
    asm volatile("cp.async.commit_group;");

    // ---- per-point layer-1 partial (overlaps the async copies) ----
    const u64* W1su = reinterpret_cast<const u64*>(W1s);
    u64 pre2 = pack2(b1s[lane * 2], b1s[lane * 2 + 1]);
    {
        const float4* pf4 = reinterpret_cast<const float4*>(pf + (size_t)p * 32);
        #pragma unroll
        for (int c4 = 0; c4 < 8; ++c4) {
            float4 f = __ldg(&pf4[c4]);
            pre2 = fma2(pack2(f.x, f.x), W1su[(c4 * 4 + 0) * 32 + lane], pre2);
            pre2 = fma2(pack2(f.y, f.y), W1su[(c4 * 4 + 1) * 32 + lane], pre2);
            pre2 = fma2(pack2(f.z, f.z), W1su[(c4 * 4 + 2) * 32 + lane], pre2);
            pre2 = fma2(pack2(f.w, f.w), W1su[(c4 * 4 + 3) * 32 + lane], pre2);
        }
    }
    u64 w1rx2 = W1su[32 * 32 + lane];
    u64 w1ry2 = W1su[33 * 32 + lane];
    u64 w1rz2 = W1su[34 * 32 + lane];

    asm volatile("cp.async.wait_group 0;");

    // ---- Phase B1: edge layer-1 (reads staged Gpre pair, writes h1 in place) ----
    u64* h1u = reinterpret_cast<u64*>(&h1s[w][0][0]);
    #pragma unroll 4
    for (int k = 0; k < KNN; ++k) {
        int t = __shfl_sync(0xffffffffu, myt, k);
        int a = t >> 4, b = (t >> 2) & 3, c = t & 3;
        float rx = __fsub_rn(lins[ix0 + a], qx);
        float ry = __fsub_rn(lins[iy0 + b], qy);
        float rz = __fsub_rn(lins[iz0 + c], qz);

        u64 gp = h1u[k * 32 + lane];           // staged Gpre pair (lane-local)
        u64 t2 = add2(pre2, gp);
        t2 = fma2(pack2(rx, rx), w1rx2, t2);
        t2 = fma2(pack2(ry, ry), w1ry2, t2);
        t2 = fma2(pack2(rz, rz), w1rz2, t2);
        h1u[k * 32 + lane] = gelu2(t2, C0, C1, NL2E, ONE2);
    }
    __syncwarp();

    // ---- Phase B2: layer-2 (packed dot) + gelu + accumulate ----
    float b2v = b2s[lane];
    float agg = 0.0f;
    #pragma unroll 2
    for (int k = 0; k < KNN; ++k) {
        const ulonglong2* hk2 = reinterpret_cast<const ulonglong2*>(&h1s[w][k][0]);
        u64 acc2 = pack2(0.0f, 0.0f);
        #pragma unroll
        for (int i2 = 0; i2 < 16; ++i2) {
            ulonglong2 hp = hk2[i2];
            acc2 = fma2(hp.x, w2p[2 * i2 + 0], acc2);
            acc2 = fma2(hp.y, w2p[2 * i2 + 1], acc2);
        }
        float a0, a1; unpack2(acc2, a0, a1);
        float acc = __fadd_rn(__fadd_rn(a0, a1), b2v);
        agg = __fadd_rn(agg, gelu_fast(acc));
    }

    // ---- mean over K, out transform (packed) ----
    aggs[w][lane] = __fmul_rn(agg, 0.0625f);
    __syncwarp();
    const u64* ag2 = reinterpret_cast<const u64*>(&aggs[w][0]);
    u64 acc2 = pack2(0.0f, 0.0f);
    #pragma unroll
    for (int i2 = 0; i2 < 16; ++i2)
        acc2 = fma2(ag2[i2], __ldg(&g_W3p[i2 * 32 + lane]), acc2);
    float a0, a1; unpack2(acc2, a0, a1);
    float acc = __fadd_rn(__fadd_rn(a0, a1), b3s[lane]);
    out[(size_t)p * 32 + lane] = gelu_fast(acc);
}

// ---------------------------------------------------------------------------
// launch
// ---------------------------------------------------------------------------
extern "C" void kernel_launch(void* const* d_in, const int* in_sizes, int n_in,
                              void* d_out, int out_size) {
    const float* gv = (const float*)d_in[0];
    const float* gf = (const float*)d_in[1];
    const float* pv = (const float*)d_in[2];
    const float* pf = (const float*)d_in[3];
    const float* W1 = (const float*)d_in[4];
    const float* b1 = (const float*)d_in[5];
    const float* W2 = (const float*)d_in[6];
    const float* b2 = (const float*)d_in[7];
    const float* W3 = (const float*)d_in[8];
    const float* b3 = (const float*)d_in[9];
    float* out = (float*)d_out;

    gpre_kernel<<<NGRID / 32, 256>>>(gf, W1, W2, W3);
    fused_kernel<<<NPTS / 8, 256>>>(gv, pv, pf, W1, b1, b2, b3, out);
}